// round 2
// baseline (speedup 1.0000x reference)
#include <cuda_runtime.h>
#include <math.h>

// Problem constants
#define BB   256      // batch
#define TT   256      // time steps
#define ID   256      // input dim
#define HH   1024     // hidden dim
#define GG   4096     // 4*H gates

typedef unsigned long long ull;

// Scratch (device globals: allocation-free rule)
__device__ float g_pre[(size_t)BB * TT * GG];   // 1 GiB: precomputed input gates
__device__ float g_wf[ID * GG];                 // W with Wy folded into row 255

// ---------------------------------------------------------------------------
// packed f32x2 helpers
// ---------------------------------------------------------------------------
__device__ __forceinline__ ull pk2(float lo, float hi) {
    ull r;
    asm("mov.b64 %0, {%1, %2};" : "=l"(r) : "f"(lo), "f"(hi));
    return r;
}
__device__ __forceinline__ void upk2(ull v, float& lo, float& hi) {
    asm("mov.b64 {%0, %1}, %2;" : "=f"(lo), "=f"(hi) : "l"(v));
}
__device__ __forceinline__ ull ffma2(ull a, ull b, ull c) {
    ull d;
    asm("fma.rn.f32x2 %0, %1, %2, %3;" : "=l"(d) : "l"(a), "l"(b), "l"(c));
    return d;
}

__device__ __forceinline__ float sigmoidf_(float x) {
    return 1.0f / (1.0f + expf(-x));
}

// ---------------------------------------------------------------------------
// Kernel 1: fold Wy into W row 255  (pre = X@W + X[:,:,255]*Wy + bias)
// ---------------------------------------------------------------------------
__global__ void fold_w_kernel(const float* __restrict__ W,
                              const float* __restrict__ Wy) {
    int idx = blockIdx.x * blockDim.x + threadIdx.x;   // 0 .. ID*GG-1
    int d = idx >> 12;            // /4096
    int g = idx & (GG - 1);
    float v = W[idx];
    if (d == ID - 1) v += Wy[g];
    g_wf[idx] = v;
}

// ---------------------------------------------------------------------------
// Kernel 2: pre[m, g] = X[m, :] @ Wf + bias[g],  M = B*T = 65536, K = 256
// 128x128 tile, BK=16, 256 threads, 8x8 per thread; FFMA2 over n-pairs.
// ---------------------------------------------------------------------------
__global__ __launch_bounds__(256) void pre_gemm_kernel(
    const float* __restrict__ X, const float* __restrict__ bias) {
    __shared__ float As[16][132];   // [k][m], padded
    __shared__ float Bs[16][128];   // [k][n]

    const int tid = threadIdx.x;
    const int tx = tid & 15;        // n dir (8 cols = 4 pairs)
    const int ty = tid >> 4;        // m dir (8 rows)
    const int nb = blockIdx.x;      // 0..31
    const int mb = blockIdx.y;      // 0..511

    ull acc[8][4];                  // [m][n-pair]
#pragma unroll
    for (int i = 0; i < 8; ++i)
#pragma unroll
        for (int j = 0; j < 4; ++j) acc[i][j] = 0ull;

    for (int kb = 0; kb < ID / 16; ++kb) {
        const int k0 = kb * 16;
        // load A tile: 128 rows x 16 k  (2 float4 per thread)
#pragma unroll
        for (int i = 0; i < 2; ++i) {
            int a_i = tid * 2 + i;
            int r = a_i >> 2;
            int kq = a_i & 3;
            float4 v = *(const float4*)(X + (size_t)(mb * 128 + r) * ID + k0 + kq * 4);
            As[kq * 4 + 0][r] = v.x;
            As[kq * 4 + 1][r] = v.y;
            As[kq * 4 + 2][r] = v.z;
            As[kq * 4 + 3][r] = v.w;
        }
        // load B tile: 16 k x 128 n (2 float4 per thread)
#pragma unroll
        for (int i = 0; i < 2; ++i) {
            int b_i = tid * 2 + i;
            int kk = b_i >> 5;
            int nq = b_i & 31;
            float4 v = *(const float4*)(g_wf + (size_t)(k0 + kk) * GG + nb * 128 + nq * 4);
            *(float4*)&Bs[kk][nq * 4] = v;
        }
        __syncthreads();
#pragma unroll
        for (int kk = 0; kk < 16; ++kk) {
            float a[8];
            *(float4*)&a[0] = *(const float4*)&As[kk][ty * 8];
            *(float4*)&a[4] = *(const float4*)&As[kk][ty * 8 + 4];
            ull b2[4];
#pragma unroll
            for (int j = 0; j < 4; ++j)
                b2[j] = *(const ull*)&Bs[kk][tx * 8 + j * 2];
#pragma unroll
            for (int i = 0; i < 8; ++i) {
                ull ap = pk2(a[i], a[i]);
#pragma unroll
                for (int j = 0; j < 4; ++j)
                    acc[i][j] = ffma2(ap, b2[j], acc[i][j]);
            }
        }
        __syncthreads();
    }

    // epilogue: add bias, store
    const int ncol = nb * 128 + tx * 8;
    float bb0[8];
#pragma unroll
    for (int j = 0; j < 8; ++j) bb0[j] = bias[ncol + j];
#pragma unroll
    for (int i = 0; i < 8; ++i) {
        size_t row = (size_t)mb * 128 + ty * 8 + i;
        float r[8];
#pragma unroll
        for (int j = 0; j < 4; ++j) upk2(acc[i][j], r[j * 2], r[j * 2 + 1]);
        float4 o0, o1;
        o0.x = r[0] + bb0[0]; o0.y = r[1] + bb0[1];
        o0.z = r[2] + bb0[2]; o0.w = r[3] + bb0[3];
        o1.x = r[4] + bb0[4]; o1.y = r[5] + bb0[5];
        o1.z = r[6] + bb0[6]; o1.w = r[7] + bb0[7];
        *(float4*)(g_pre + row * GG + ncol) = o0;
        *(float4*)(g_pre + row * GG + ncol + 4) = o1;
    }
}

// ---------------------------------------------------------------------------
// Kernel 3: one LSTM step.
// gates[b, :] = pre[b, t, :] + h_{t-1}[b, :] @ U    then cell update.
// Block tile: 64 rows (batch) x 32 j x 4 gates, 256 threads.
// Thread tile: 4 rows x 2 j (packed) x 4 gates -> 16 ull accumulators.
// A duplicated in smem so the packed broadcast is a single LDS.64.
// Double-buffered smem + register prefetch of global loads.
// ---------------------------------------------------------------------------
__global__ __launch_bounds__(256) void lstm_step_kernel(
    const float* __restrict__ U,
    float* __restrict__ hidden,      // [B][T][H]
    float* __restrict__ c_state,     // [B][H]
    float* __restrict__ h_final,     // [B][H]
    int t) {
    __shared__ float As2[2][16][132];   // h_prev, duplicated: [buf][k][row*2(+1)]
    __shared__ float Us[2][16][4][32];  // U tile: [buf][k][gate][j]

    const int tid = threadIdx.x;
    const int tx = tid & 15;          // j-group: 2 j's
    const int ty = tid >> 4;          // row-group: 4 rows
    const int jb = blockIdx.x;        // 0..31
    const int rb = blockIdx.y;        // 0..3

    ull acc[4][4];                    // [row][gate], packed j-pair
#pragma unroll
    for (int m = 0; m < 4; ++m)
#pragma unroll
        for (int g = 0; g < 4; ++g) acc[m][g] = 0ull;

    if (t > 0) {
        // loader thread mapping
        const int lr = tid >> 2;          // A: row 0..63
        const int lkq = tid & 3;          // A: k-quad 0..3
        const float* hrow = hidden + ((size_t)(rb * 64 + lr) * TT + (t - 1)) * HH + lkq * 4;
        // U loader: 2 float4 per thread
        int ukk[2], ugate[2], ujq[2];
#pragma unroll
        for (int h = 0; h < 2; ++h) {
            int idx = tid * 2 + h;
            ukk[h] = idx >> 5;
            ugate[h] = (idx >> 3) & 3;
            ujq[h] = idx & 7;
        }
        const float* ubase = U + jb * 32;

        float4 av;                        // A prefetch regs
        float4 uv[2];                     // U prefetch regs

        // prefetch k-tile 0
        av = *(const float4*)(hrow);
#pragma unroll
        for (int h = 0; h < 2; ++h)
            uv[h] = *(const float4*)(ubase + (size_t)ukk[h] * GG + ugate[h] * HH + ujq[h] * 4);
        // store to buf 0
        {
            float va[4] = {av.x, av.y, av.z, av.w};
#pragma unroll
            for (int i = 0; i < 4; ++i)
                *(ull*)&As2[0][lkq * 4 + i][lr * 2] = pk2(va[i], va[i]);
#pragma unroll
            for (int h = 0; h < 2; ++h)
                *(float4*)&Us[0][ukk[h]][ugate[h]][ujq[h] * 4] = uv[h];
        }
        __syncthreads();

        for (int kb = 0; kb < HH / 16; ++kb) {
            const int buf = kb & 1;
            // prefetch next k-tile into regs (overlaps with compute)
            if (kb + 1 < HH / 16) {
                const int k0n = (kb + 1) * 16;
                av = *(const float4*)(hrow + k0n);
#pragma unroll
                for (int h = 0; h < 2; ++h)
                    uv[h] = *(const float4*)(ubase + (size_t)(k0n + ukk[h]) * GG +
                                             ugate[h] * HH + ujq[h] * 4);
            }
            // compute on current buffer
#pragma unroll
            for (int kk = 0; kk < 16; ++kk) {
                ull a2[4], u2[4];
#pragma unroll
                for (int m = 0; m < 4; ++m)
                    a2[m] = *(const ull*)&As2[buf][kk][(ty * 4 + m) * 2];
#pragma unroll
                for (int g = 0; g < 4; ++g)
                    u2[g] = *(const ull*)&Us[buf][kk][g][tx * 2];
#pragma unroll
                for (int m = 0; m < 4; ++m)
#pragma unroll
                    for (int g = 0; g < 4; ++g)
                        acc[m][g] = ffma2(a2[m], u2[g], acc[m][g]);
            }
            // store prefetched tile into the other buffer
            if (kb + 1 < HH / 16) {
                __syncthreads();   // everyone done reading buf^1 (from prev iter)
                const int nbuf = buf ^ 1;
                float va[4] = {av.x, av.y, av.z, av.w};
#pragma unroll
                for (int i = 0; i < 4; ++i)
                    *(ull*)&As2[nbuf][lkq * 4 + i][lr * 2] = pk2(va[i], va[i]);
#pragma unroll
                for (int h = 0; h < 2; ++h)
                    *(float4*)&Us[nbuf][ukk[h]][ugate[h]][ujq[h] * 4] = uv[h];
                __syncthreads();
            }
        }
    }

    // epilogue: gates -> cell update (packed over the j-pair)
    const int j0 = jb * 32 + tx * 2;
#pragma unroll
    for (int m = 0; m < 4; ++m) {
        const int b = rb * 64 + ty * 4 + m;
        const float* prow = g_pre + ((size_t)b * TT + t) * GG + j0;
        float glo[4], ghi[4];
#pragma unroll
        for (int g = 0; g < 4; ++g) {
            float plo, phi;
            upk2(*(const ull*)&prow[g * HH], plo, phi);
            float alo, ahi;
            upk2(acc[m][g], alo, ahi);
            glo[g] = alo + plo;
            ghi[g] = ahi + phi;
        }
        float c_lo = 0.f, c_hi = 0.f;
        if (t > 0) upk2(*(const ull*)&c_state[b * HH + j0], c_lo, c_hi);

        float i_lo = sigmoidf_(glo[0]), i_hi = sigmoidf_(ghi[0]);
        float f_lo = sigmoidf_(glo[1]), f_hi = sigmoidf_(ghi[1]);
        float g_lo = tanhf(glo[2]),     g_hi = tanhf(ghi[2]);
        float o_lo = sigmoidf_(glo[3]), o_hi = sigmoidf_(ghi[3]);

        float cn_lo = f_lo * c_lo + i_lo * g_lo;
        float cn_hi = f_hi * c_hi + i_hi * g_hi;
        float hn_lo = o_lo * tanhf(cn_lo);
        float hn_hi = o_hi * tanhf(cn_hi);

        *(ull*)&c_state[b * HH + j0] = pk2(cn_lo, cn_hi);
        *(ull*)&hidden[(size_t)b * TT * HH + (size_t)t * HH + j0] = pk2(hn_lo, hn_hi);
        if (t == TT - 1)
            *(ull*)&h_final[b * HH + j0] = pk2(hn_lo, hn_hi);
    }
}

// ---------------------------------------------------------------------------
// Kernel 4: y_pred[b] = h_final[b,:] . fc_w + fc_b
// ---------------------------------------------------------------------------
__global__ void fc_kernel(const float* __restrict__ h_final,
                          const float* __restrict__ fc_w,
                          const float* __restrict__ fc_b,
                          float* __restrict__ y_pred) {
    int b = blockIdx.x;
    int tid = threadIdx.x;   // 256
    float s = 0.f;
    for (int k = tid; k < HH; k += 256)
        s += h_final[b * HH + k] * fc_w[k];
#pragma unroll
    for (int off = 16; off > 0; off >>= 1)
        s += __shfl_down_sync(0xffffffffu, s, off);
    __shared__ float red[8];
    if ((tid & 31) == 0) red[tid >> 5] = s;
    __syncthreads();
    if (tid == 0) {
        float tot = 0.f;
#pragma unroll
        for (int w = 0; w < 8; ++w) tot += red[w];
        y_pred[b] = tot + fc_b[0];
    }
}

// ---------------------------------------------------------------------------
extern "C" void kernel_launch(void* const* d_in, const int* in_sizes, int n_in,
                              void* d_out, int out_size) {
    const float* X    = (const float*)d_in[0];
    const float* W    = (const float*)d_in[1];
    const float* U    = (const float*)d_in[2];
    const float* bias = (const float*)d_in[3];
    const float* Wy   = (const float*)d_in[4];
    const float* fc_w = (const float*)d_in[5];
    const float* fc_b = (const float*)d_in[6];

    float* out = (float*)d_out;
    // output layout: y_pred[256] | hidden_seq[B*T*H] | h_t[B*H] | c_t[B*H]
    float* y_pred  = out;
    float* hidden  = out + 256;
    float* h_final = hidden + (size_t)BB * TT * HH;
    float* c_state = h_final + (size_t)BB * HH;

    fold_w_kernel<<<1024, 1024>>>(W, Wy);
    pre_gemm_kernel<<<dim3(GG / 128, (BB * TT) / 128), 256>>>(X, bias);
    for (int t = 0; t < TT; ++t)
        lstm_step_kernel<<<dim3(HH / 32, BB / 64), 256>>>(U, hidden, c_state, h_final, t);
    fc_kernel<<<BB, 256>>>(h_final, fc_w, fc_b, y_pred);
}

// round 4
// speedup vs baseline: 2.5098x; 2.5098x over previous
#include <cuda_runtime.h>
#include <cuda_bf16.h>
#include <math.h>
#include <stdint.h>

// Problem constants
#define BB   256      // batch
#define TT   256      // time steps
#define ID   256      // input dim
#define HH   1024     // hidden dim
#define GG   4096     // 4*H gates

// Step-kernel tiling
#define KC          64                 // K chunk
#define NCH         (HH / KC)          // 16 chunks
#define STAGE_BYTES 49152              // Ahi(8K) Alo(8K) Bhi(16K) Blo(16K)
#define DYN_SMEM    (2 * STAGE_BYTES)  // 96 KB

typedef unsigned long long ull;

// Scratch (device globals: allocation-free rule)
__device__ float g_pre[(size_t)BB * TT * GG];   // 1 GiB input-gate precompute
__device__ float g_wf[ID * GG];                 // W with Wy folded into row 255
__device__ __nv_bfloat16 g_ut_hi[(size_t)GG * HH];   // U^T split hi [4096][1024]
__device__ __nv_bfloat16 g_ut_lo[(size_t)GG * HH];   // U^T split lo
__device__ __nv_bfloat16 g_hbf_hi[2][BB * HH];       // h ping-pong bf16 hi
__device__ __nv_bfloat16 g_hbf_lo[2][BB * HH];       // h ping-pong bf16 lo

// ---------------------------------------------------------------------------
// helpers
// ---------------------------------------------------------------------------
__device__ __forceinline__ ull pk2(float lo, float hi) {
    ull r; asm("mov.b64 %0, {%1, %2};" : "=l"(r) : "f"(lo), "f"(hi)); return r;
}
__device__ __forceinline__ void upk2(ull v, float& lo, float& hi) {
    asm("mov.b64 {%0, %1}, %2;" : "=f"(lo), "=f"(hi) : "l"(v));
}
__device__ __forceinline__ ull ffma2(ull a, ull b, ull c) {
    ull d; asm("fma.rn.f32x2 %0, %1, %2, %3;" : "=l"(d) : "l"(a), "l"(b), "l"(c)); return d;
}
__device__ __forceinline__ float sigmoidf_(float x) {
    return 1.0f / (1.0f + expf(-x));
}
__device__ __forceinline__ void cp_async16(uint32_t dst, const void* src) {
    asm volatile("cp.async.cg.shared.global [%0], [%1], 16;" :: "r"(dst), "l"(src));
}
__device__ __forceinline__ void ldsm_x4(uint32_t* r, uint32_t addr) {
    asm volatile("ldmatrix.sync.aligned.m8n8.x4.shared.b16 {%0,%1,%2,%3}, [%4];"
                 : "=r"(r[0]), "=r"(r[1]), "=r"(r[2]), "=r"(r[3]) : "r"(addr));
}
__device__ __forceinline__ void ldsm_x2(uint32_t* r, uint32_t addr) {
    asm volatile("ldmatrix.sync.aligned.m8n8.x2.shared.b16 {%0,%1}, [%2];"
                 : "=r"(r[0]), "=r"(r[1]) : "r"(addr));
}
__device__ __forceinline__ void mma_bf16(float* d, const uint32_t* a, const uint32_t* b) {
    asm volatile("mma.sync.aligned.m16n8k16.row.col.f32.bf16.bf16.f32 "
                 "{%0,%1,%2,%3}, {%4,%5,%6,%7}, {%8,%9}, {%0,%1,%2,%3};"
                 : "+f"(d[0]), "+f"(d[1]), "+f"(d[2]), "+f"(d[3])
                 : "r"(a[0]), "r"(a[1]), "r"(a[2]), "r"(a[3]), "r"(b[0]), "r"(b[1]));
}

// ---------------------------------------------------------------------------
// Kernel 1: fold Wy into W row 255
// ---------------------------------------------------------------------------
__global__ void fold_w_kernel(const float* __restrict__ W,
                              const float* __restrict__ Wy) {
    int idx = blockIdx.x * blockDim.x + threadIdx.x;
    int d = idx >> 12;
    int g = idx & (GG - 1);
    float v = W[idx];
    if (d == ID - 1) v += Wy[g];
    g_wf[idx] = v;
}

// ---------------------------------------------------------------------------
// Kernel 1b: U^T bf16 split: g_ut_hi/lo[g][k] = split(U[k][g])
// ---------------------------------------------------------------------------
__global__ void u_split_kernel(const float* __restrict__ U) {
    __shared__ float tile[32][33];
    const int kb = blockIdx.x * 32;
    const int gb = blockIdx.y * 32;
    const int tx = threadIdx.x & 31;
    const int ty = threadIdx.x >> 5;   // 0..7
#pragma unroll
    for (int i = 0; i < 32; i += 8)
        tile[ty + i][tx] = U[(size_t)(kb + ty + i) * GG + gb + tx];
    __syncthreads();
#pragma unroll
    for (int i = 0; i < 32; i += 8) {
        int g = gb + ty + i;
        int k = kb + tx;
        float v = tile[tx][ty + i];
        __nv_bfloat16 hi = __float2bfloat16(v);
        __nv_bfloat16 lo = __float2bfloat16(v - __bfloat162float(hi));
        g_ut_hi[(size_t)g * HH + k] = hi;
        g_ut_lo[(size_t)g * HH + k] = lo;
    }
}

// ---------------------------------------------------------------------------
// Kernel 2: pre[m, g] = X[m, :] @ Wf + bias[g]  (fp32 FFMA2)
// ---------------------------------------------------------------------------
__global__ __launch_bounds__(256) void pre_gemm_kernel(
    const float* __restrict__ X, const float* __restrict__ bias) {
    __shared__ float As[16][132];
    __shared__ float Bs[16][128];

    const int tid = threadIdx.x;
    const int tx = tid & 15;
    const int ty = tid >> 4;
    const int nb = blockIdx.x;
    const int mb = blockIdx.y;

    ull acc[8][4];
#pragma unroll
    for (int i = 0; i < 8; ++i)
#pragma unroll
        for (int j = 0; j < 4; ++j) acc[i][j] = 0ull;

    for (int kb = 0; kb < ID / 16; ++kb) {
        const int k0 = kb * 16;
#pragma unroll
        for (int i = 0; i < 2; ++i) {
            int a_i = tid * 2 + i;
            int r = a_i >> 2;
            int kq = a_i & 3;
            float4 v = *(const float4*)(X + (size_t)(mb * 128 + r) * ID + k0 + kq * 4);
            As[kq * 4 + 0][r] = v.x;
            As[kq * 4 + 1][r] = v.y;
            As[kq * 4 + 2][r] = v.z;
            As[kq * 4 + 3][r] = v.w;
        }
#pragma unroll
        for (int i = 0; i < 2; ++i) {
            int b_i = tid * 2 + i;
            int kk = b_i >> 5;
            int nq = b_i & 31;
            float4 v = *(const float4*)(g_wf + (size_t)(k0 + kk) * GG + nb * 128 + nq * 4);
            *(float4*)&Bs[kk][nq * 4] = v;
        }
        __syncthreads();
#pragma unroll
        for (int kk = 0; kk < 16; ++kk) {
            float a[8];
            *(float4*)&a[0] = *(const float4*)&As[kk][ty * 8];
            *(float4*)&a[4] = *(const float4*)&As[kk][ty * 8 + 4];
            ull b2[4];
#pragma unroll
            for (int j = 0; j < 4; ++j)
                b2[j] = *(const ull*)&Bs[kk][tx * 8 + j * 2];
#pragma unroll
            for (int i = 0; i < 8; ++i) {
                ull ap = pk2(a[i], a[i]);
#pragma unroll
                for (int j = 0; j < 4; ++j)
                    acc[i][j] = ffma2(ap, b2[j], acc[i][j]);
            }
        }
        __syncthreads();
    }

    const int ncol = nb * 128 + tx * 8;
    float bb0[8];
#pragma unroll
    for (int j = 0; j < 8; ++j) bb0[j] = bias[ncol + j];
#pragma unroll
    for (int i = 0; i < 8; ++i) {
        size_t row = (size_t)mb * 128 + ty * 8 + i;
        float r[8];
#pragma unroll
        for (int j = 0; j < 4; ++j) upk2(acc[i][j], r[j * 2], r[j * 2 + 1]);
        float4 o0, o1;
        o0.x = r[0] + bb0[0]; o0.y = r[1] + bb0[1];
        o0.z = r[2] + bb0[2]; o0.w = r[3] + bb0[3];
        o1.x = r[4] + bb0[4]; o1.y = r[5] + bb0[5];
        o1.z = r[6] + bb0[6]; o1.w = r[7] + bb0[7];
        *(float4*)(g_pre + row * GG + ncol) = o0;
        *(float4*)(g_pre + row * GG + ncol + 4) = o1;
    }
}

// ---------------------------------------------------------------------------
// Kernel 3: mma.sync LSTM step (HMMA bf16, 3-pass split).
// CTA: 64 batch x [4 gates x 32 j]; grid (32, 4) = 128 CTAs; 256 threads.
// Warps: 4 m-warps x 2 j-warps. Warp tile: m16 x j16 x 4 gates.
// Gates = pre + Hhi@Uhi + Hhi@Ulo + Hlo@Uhi, fp32 accum; fused cell update.
// ---------------------------------------------------------------------------
__global__ __launch_bounds__(256, 1) void lstm_step_mma(
    float* __restrict__ hidden,      // [B][T][H]
    float* __restrict__ c_state,     // [B][H]
    float* __restrict__ h_final,     // [B][H]
    int t) {
    extern __shared__ char dsm[];
    const int tid = threadIdx.x;
    const int wid = tid >> 5;
    const int lane = tid & 31;
    const int jt = blockIdx.x;       // 0..31
    const int mt = blockIdx.y;       // 0..3
    const int mwarp = wid >> 1;      // 0..3
    const int jwarp = wid & 1;       // 0..1

    float acc[4][2][4];              // [gate][n-block][reg]
#pragma unroll
    for (int g = 0; g < 4; ++g)
#pragma unroll
        for (int nb = 0; nb < 2; ++nb)
#pragma unroll
            for (int r = 0; r < 4; ++r) acc[g][nb][r] = 0.f;

    const uint32_t smem0 = (uint32_t)__cvta_generic_to_shared(dsm);

    if (t > 0) {
        const __nv_bfloat16* hphi = g_hbf_hi[(t - 1) & 1];
        const __nv_bfloat16* hplo = g_hbf_lo[(t - 1) & 1];

        auto load_chunk = [&](int c, int s) {
            const int k0 = c * KC;
            const uint32_t sb = smem0 + s * STAGE_BYTES;
            // A: 2 mats x 64 rows x 8 granules = 1024
#pragma unroll
            for (int i = 0; i < 4; ++i) {
                int ga = i * 256 + tid;
                int mat = ga >> 9;
                int row = (ga >> 3) & 63;
                int gk = ga & 7;
                const __nv_bfloat16* src = (mat ? hplo : hphi) +
                    (size_t)(mt * 64 + row) * HH + k0 + gk * 8;
                uint32_t dst = sb + mat * 8192 + row * 128 + ((gk ^ (row & 7)) << 4);
                cp_async16(dst, src);
            }
            // B: 2 mats x 128 rows (4 gates x 32 j) x 8 granules = 2048
#pragma unroll
            for (int i = 0; i < 8; ++i) {
                int gb = i * 256 + tid;
                int mat = gb >> 10;
                int row = (gb >> 3) & 127;
                int gk = gb & 7;
                int grow = (row >> 5) * HH + jt * 32 + (row & 31);   // gate*1024 + j
                const __nv_bfloat16* src = (mat ? g_ut_lo : g_ut_hi) +
                    (size_t)grow * HH + k0 + gk * 8;
                uint32_t dst = sb + 16384 + mat * 16384 + row * 128 +
                               ((gk ^ (row & 7)) << 4);
                cp_async16(dst, src);
            }
            asm volatile("cp.async.commit_group;" ::: "memory");
        };

        load_chunk(0, 0);
        asm volatile("cp.async.wait_group 0;" ::: "memory");
        __syncthreads();

        const uint32_t arow = mwarp * 16 + (lane & 15);
        const uint32_t brow_base = jwarp * 16 + (lane & 7);

        for (int c = 0; c < NCH; ++c) {
            const int s = c & 1;
            if (c + 1 < NCH) load_chunk(c + 1, s ^ 1);
            const uint32_t sb = smem0 + s * STAGE_BYTES;
#pragma unroll
            for (int ks = 0; ks < KC / 16; ++ks) {
                uint32_t a_hi[4], a_lo[4];
                {
                    int gk = ks * 2 + (lane >> 4);
                    uint32_t off = arow * 128 + ((gk ^ (arow & 7)) << 4);
                    ldsm_x4(a_hi, sb + off);
                    ldsm_x4(a_lo, sb + 8192 + off);
                }
#pragma unroll
                for (int g = 0; g < 4; ++g) {
#pragma unroll
                    for (int nb = 0; nb < 2; ++nb) {
                        uint32_t row = g * 32 + brow_base + nb * 8;
                        int gk = ks * 2 + ((lane >> 3) & 1);
                        uint32_t off = row * 128 + ((gk ^ (row & 7)) << 4);
                        uint32_t b_hi[2], b_lo[2];
                        ldsm_x2(b_hi, sb + 16384 + off);
                        ldsm_x2(b_lo, sb + 32768 + off);
                        mma_bf16(acc[g][nb], a_hi, b_hi);
                        mma_bf16(acc[g][nb], a_hi, b_lo);
                        mma_bf16(acc[g][nb], a_lo, b_hi);
                    }
                }
            }
            if (c + 1 < NCH) {
                asm volatile("cp.async.wait_group 0;" ::: "memory");
                __syncthreads();
            }
        }
    }

    // ---- fused cell-update epilogue ----
    const int b_base = mt * 64 + mwarp * 16 + (lane >> 2);
#pragma unroll
    for (int rh = 0; rh < 2; ++rh) {
        const int b = b_base + rh * 8;
        const float* prow = g_pre + ((size_t)b * TT + t) * GG;
        float* crow = c_state + (size_t)b * HH;
        float* hrow = hidden + ((size_t)b * TT + t) * HH;
        __nv_bfloat16* bh = g_hbf_hi[t & 1] + (size_t)b * HH;
        __nv_bfloat16* bl = g_hbf_lo[t & 1] + (size_t)b * HH;
#pragma unroll
        for (int nb = 0; nb < 2; ++nb) {
            const int j = jt * 32 + jwarp * 16 + nb * 8 + (lane & 3) * 2;
            float2 pi = *(const float2*)(prow + 0 * HH + j);
            float2 pf = *(const float2*)(prow + 1 * HH + j);
            float2 pg = *(const float2*)(prow + 2 * HH + j);
            float2 po = *(const float2*)(prow + 3 * HH + j);
            float2 co = (t > 0) ? *(const float2*)(crow + j)
                                : make_float2(0.f, 0.f);
            const int r0 = rh * 2;
            float i0 = sigmoidf_(acc[0][nb][r0]     + pi.x);
            float i1 = sigmoidf_(acc[0][nb][r0 + 1] + pi.y);
            float f0 = sigmoidf_(acc[1][nb][r0]     + pf.x);
            float f1 = sigmoidf_(acc[1][nb][r0 + 1] + pf.y);
            float g0 = tanhf(acc[2][nb][r0]     + pg.x);
            float g1 = tanhf(acc[2][nb][r0 + 1] + pg.y);
            float o0 = sigmoidf_(acc[3][nb][r0]     + po.x);
            float o1 = sigmoidf_(acc[3][nb][r0 + 1] + po.y);
            float cn0 = f0 * co.x + i0 * g0;
            float cn1 = f1 * co.y + i1 * g1;
            float hn0 = o0 * tanhf(cn0);
            float hn1 = o1 * tanhf(cn1);
            *(float2*)(crow + j) = make_float2(cn0, cn1);
            *(float2*)(hrow + j) = make_float2(hn0, hn1);
            __nv_bfloat16 h0h = __float2bfloat16(hn0);
            __nv_bfloat16 h1h = __float2bfloat16(hn1);
            __nv_bfloat16 h0l = __float2bfloat16(hn0 - __bfloat162float(h0h));
            __nv_bfloat16 h1l = __float2bfloat16(hn1 - __bfloat162float(h1h));
            *(__nv_bfloat162*)(bh + j) = __nv_bfloat162(h0h, h1h);
            *(__nv_bfloat162*)(bl + j) = __nv_bfloat162(h0l, h1l);
            if (t == TT - 1)
                *(float2*)(h_final + (size_t)b * HH + j) = make_float2(hn0, hn1);
        }
    }
}

// ---------------------------------------------------------------------------
// Kernel 4: y_pred[b] = h_final[b,:] . fc_w + fc_b
// ---------------------------------------------------------------------------
__global__ void fc_kernel(const float* __restrict__ h_final,
                          const float* __restrict__ fc_w,
                          const float* __restrict__ fc_b,
                          float* __restrict__ y_pred) {
    int b = blockIdx.x;
    int tid = threadIdx.x;
    float s = 0.f;
    for (int k = tid; k < HH; k += 256)
        s += h_final[b * HH + k] * fc_w[k];
#pragma unroll
    for (int off = 16; off > 0; off >>= 1)
        s += __shfl_down_sync(0xffffffffu, s, off);
    __shared__ float red[8];
    if ((tid & 31) == 0) red[tid >> 5] = s;
    __syncthreads();
    if (tid == 0) {
        float tot = 0.f;
#pragma unroll
        for (int w = 0; w < 8; ++w) tot += red[w];
        y_pred[b] = tot + fc_b[0];
    }
}

// ---------------------------------------------------------------------------
extern "C" void kernel_launch(void* const* d_in, const int* in_sizes, int n_in,
                              void* d_out, int out_size) {
    const float* X    = (const float*)d_in[0];
    const float* W    = (const float*)d_in[1];
    const float* U    = (const float*)d_in[2];
    const float* bias = (const float*)d_in[3];
    const float* Wy   = (const float*)d_in[4];
    const float* fc_w = (const float*)d_in[5];
    const float* fc_b = (const float*)d_in[6];

    float* out = (float*)d_out;
    // output layout: y_pred[256] | hidden_seq[B*T*H] | h_t[B*H] | c_t[B*H]
    float* y_pred  = out;
    float* hidden  = out + 256;
    float* h_final = hidden + (size_t)BB * TT * HH;
    float* c_state = h_final + (size_t)BB * HH;

    cudaFuncSetAttribute(lstm_step_mma, cudaFuncAttributeMaxDynamicSharedMemorySize,
                         DYN_SMEM);

    fold_w_kernel<<<1024, 1024>>>(W, Wy);
    u_split_kernel<<<dim3(HH / 32, GG / 32), 256>>>(U);
    pre_gemm_kernel<<<dim3(GG / 128, (BB * TT) / 128), 256>>>(X, bias);
    for (int t = 0; t < TT; ++t)
        lstm_step_mma<<<dim3(HH / 32, BB / 64), 256, DYN_SMEM>>>(hidden, c_state,
                                                                 h_final, t);
    fc_kernel<<<BB, 256>>>(h_final, fc_w, fc_b, y_pred);
}

// round 5
// speedup vs baseline: 3.2300x; 1.2869x over previous
#include <cuda_runtime.h>
#include <cuda_bf16.h>
#include <math.h>
#include <stdint.h>

// Problem constants
#define BB   256      // batch
#define TT   256      // time steps
#define ID   256      // input dim
#define HH   1024     // hidden dim
#define GG   4096     // 4*H gates

// Step-kernel tiling
#define KC          64                 // K chunk
#define NCH         (HH / KC)          // 16 chunks
#define STAGE_BYTES 49152              // Ahi(8K) Alo(8K) Bhi(16K) Blo(16K)
#define DYN_SMEM    (2 * STAGE_BYTES)  // 96 KB
// Pre-GEMM smem: Ahi/Alo 16K each + Bhi/Blo 16K each (single stage, KC=64)
#define PRE_SMEM    65536

typedef unsigned long long ull;

// Scratch (device globals: allocation-free rule)
__device__ float g_pre[(size_t)BB * TT * GG];        // 1 GiB input-gate precompute
__device__ __nv_bfloat16 g_ut_hi[(size_t)GG * HH];   // U^T split hi [4096][1024]
__device__ __nv_bfloat16 g_ut_lo[(size_t)GG * HH];   // U^T split lo
__device__ __nv_bfloat16 g_wt_hi[GG * ID];           // folded W^T split hi [4096][256]
__device__ __nv_bfloat16 g_wt_lo[GG * ID];           // folded W^T split lo
__device__ __nv_bfloat16 g_x_hi[(size_t)BB * TT * ID];   // X split hi
__device__ __nv_bfloat16 g_x_lo[(size_t)BB * TT * ID];   // X split lo
__device__ __nv_bfloat16 g_hbf_hi[2][BB * HH];       // h ping-pong bf16 hi
__device__ __nv_bfloat16 g_hbf_lo[2][BB * HH];       // h ping-pong bf16 lo
__device__ unsigned int g_bar;                        // global step barrier

// ---------------------------------------------------------------------------
// helpers
// ---------------------------------------------------------------------------
__device__ __forceinline__ float sigmoidf_(float x) {
    return 1.0f / (1.0f + expf(-x));
}
__device__ __forceinline__ void cp_async16(uint32_t dst, const void* src) {
    asm volatile("cp.async.cg.shared.global [%0], [%1], 16;" :: "r"(dst), "l"(src));
}
__device__ __forceinline__ void ldsm_x4(uint32_t* r, uint32_t addr) {
    asm volatile("ldmatrix.sync.aligned.m8n8.x4.shared.b16 {%0,%1,%2,%3}, [%4];"
                 : "=r"(r[0]), "=r"(r[1]), "=r"(r[2]), "=r"(r[3]) : "r"(addr));
}
__device__ __forceinline__ void ldsm_x2(uint32_t* r, uint32_t addr) {
    asm volatile("ldmatrix.sync.aligned.m8n8.x2.shared.b16 {%0,%1}, [%2];"
                 : "=r"(r[0]), "=r"(r[1]) : "r"(addr));
}
__device__ __forceinline__ void mma_bf16(float* d, const uint32_t* a, const uint32_t* b) {
    asm volatile("mma.sync.aligned.m16n8k16.row.col.f32.bf16.bf16.f32 "
                 "{%0,%1,%2,%3}, {%4,%5,%6,%7}, {%8,%9}, {%0,%1,%2,%3};"
                 : "+f"(d[0]), "+f"(d[1]), "+f"(d[2]), "+f"(d[3])
                 : "r"(a[0]), "r"(a[1]), "r"(a[2]), "r"(a[3]), "r"(b[0]), "r"(b[1]));
}

// ---------------------------------------------------------------------------
// Kernel A: fold Wy into W row 255, transpose, bf16-split -> g_wt_hi/lo[g][k]
// ---------------------------------------------------------------------------
__global__ void wt_split_kernel(const float* __restrict__ W,
                                const float* __restrict__ Wy) {
    __shared__ float tile[32][33];
    const int kb = blockIdx.x * 32;   // over ID
    const int gb = blockIdx.y * 32;   // over GG
    const int tx = threadIdx.x & 31;
    const int ty = threadIdx.x >> 5;  // 0..7
#pragma unroll
    for (int i = 0; i < 32; i += 8) {
        int krow = kb + ty + i;
        float v = W[(size_t)krow * GG + gb + tx];
        if (krow == ID - 1) v += Wy[gb + tx];
        tile[ty + i][tx] = v;
    }
    __syncthreads();
#pragma unroll
    for (int i = 0; i < 32; i += 8) {
        int g = gb + ty + i;
        int k = kb + tx;
        float v = tile[tx][ty + i];
        __nv_bfloat16 hi = __float2bfloat16(v);
        __nv_bfloat16 lo = __float2bfloat16(v - __bfloat162float(hi));
        g_wt_hi[g * ID + k] = hi;
        g_wt_lo[g * ID + k] = lo;
    }
}

// ---------------------------------------------------------------------------
// Kernel B: U^T bf16 split: g_ut_hi/lo[g][k] = split(U[k][g])
// ---------------------------------------------------------------------------
__global__ void u_split_kernel(const float* __restrict__ U) {
    __shared__ float tile[32][33];
    const int kb = blockIdx.x * 32;
    const int gb = blockIdx.y * 32;
    const int tx = threadIdx.x & 31;
    const int ty = threadIdx.x >> 5;
#pragma unroll
    for (int i = 0; i < 32; i += 8)
        tile[ty + i][tx] = U[(size_t)(kb + ty + i) * GG + gb + tx];
    __syncthreads();
#pragma unroll
    for (int i = 0; i < 32; i += 8) {
        int g = gb + ty + i;
        int k = kb + tx;
        float v = tile[tx][ty + i];
        __nv_bfloat16 hi = __float2bfloat16(v);
        __nv_bfloat16 lo = __float2bfloat16(v - __bfloat162float(hi));
        g_ut_hi[(size_t)g * HH + k] = hi;
        g_ut_lo[(size_t)g * HH + k] = lo;
    }
}

// ---------------------------------------------------------------------------
// Kernel C: X bf16 split (elementwise)
// ---------------------------------------------------------------------------
__global__ void x_split_kernel(const float* __restrict__ X) {
    size_t i4 = (size_t)blockIdx.x * blockDim.x + threadIdx.x;
    float4 v = *(const float4*)(X + i4 * 4);
    float f[4] = {v.x, v.y, v.z, v.w};
    __nv_bfloat16 hi[4], lo[4];
#pragma unroll
    for (int e = 0; e < 4; ++e) {
        hi[e] = __float2bfloat16(f[e]);
        lo[e] = __float2bfloat16(f[e] - __bfloat162float(hi[e]));
    }
    *(__nv_bfloat162*)(g_x_hi + i4 * 4)     = __nv_bfloat162(hi[0], hi[1]);
    *(__nv_bfloat162*)(g_x_hi + i4 * 4 + 2) = __nv_bfloat162(hi[2], hi[3]);
    *(__nv_bfloat162*)(g_x_lo + i4 * 4)     = __nv_bfloat162(lo[0], lo[1]);
    *(__nv_bfloat162*)(g_x_lo + i4 * 4 + 2) = __nv_bfloat162(lo[2], lo[3]);
}

// ---------------------------------------------------------------------------
// Kernel D: tensorized pre-GEMM.  g_pre[m, g] = X[m,:] @ Wf[:, g] + bias[g]
// CTA 128m x 128n, K=256 in 4 chunks of 64, single-stage smem, bf16 3-pass.
// 8 warps = 4 m-warps x 2 n-warps; warp tile m32 x n64.
// ---------------------------------------------------------------------------
__global__ __launch_bounds__(256, 2) void pre_gemm_mma(
    const float* __restrict__ bias) {
    extern __shared__ char dsm[];
    const uint32_t sA = (uint32_t)__cvta_generic_to_shared(dsm);        // 2 x 16KB
    const uint32_t sB = sA + 32768;                                      // 2 x 16KB

    const int tid = threadIdx.x;
    const int wid = tid >> 5;
    const int lane = tid & 31;
    const int mwarp = wid >> 1;       // 0..3
    const int nwarp = wid & 1;        // 0..1
    const int m0 = blockIdx.y * 128;
    const int n0 = blockIdx.x * 128;

    float acc[2][8][4];
#pragma unroll
    for (int mb = 0; mb < 2; ++mb)
#pragma unroll
        for (int nb = 0; nb < 8; ++nb)
#pragma unroll
            for (int r = 0; r < 4; ++r) acc[mb][nb][r] = 0.f;

    for (int kb = 0; kb < ID / KC; ++kb) {
        const int k0 = kb * KC;
        __syncthreads();
        // A: 2 mats x 128 rows x 8 granules(16B) = 2048 -> 8 per thread
#pragma unroll
        for (int i = 0; i < 8; ++i) {
            int idx = i * 256 + tid;
            int mat = idx >> 10;
            int row = (idx >> 3) & 127;
            int gk = idx & 7;
            const __nv_bfloat16* src = (mat ? g_x_lo : g_x_hi) +
                (size_t)(m0 + row) * ID + k0 + gk * 8;
            uint32_t dst = sA + mat * 16384 + row * 128 + ((gk ^ (row & 7)) << 4);
            cp_async16(dst, src);
        }
        // B: 2 mats x 128 rows x 8 granules = 2048 -> 8 per thread
#pragma unroll
        for (int i = 0; i < 8; ++i) {
            int idx = i * 256 + tid;
            int mat = idx >> 10;
            int row = (idx >> 3) & 127;
            int gk = idx & 7;
            const __nv_bfloat16* src = (mat ? g_wt_lo : g_wt_hi) +
                (size_t)(n0 + row) * ID + k0 + gk * 8;
            uint32_t dst = sB + mat * 16384 + row * 128 + ((gk ^ (row & 7)) << 4);
            cp_async16(dst, src);
        }
        asm volatile("cp.async.commit_group;" ::: "memory");
        asm volatile("cp.async.wait_group 0;" ::: "memory");
        __syncthreads();

#pragma unroll
        for (int ks = 0; ks < KC / 16; ++ks) {
            uint32_t a_hi[2][4], a_lo[2][4];
#pragma unroll
            for (int mb = 0; mb < 2; ++mb) {
                uint32_t arow = mwarp * 32 + mb * 16 + (lane & 15);
                int gk = ks * 2 + (lane >> 4);
                uint32_t off = arow * 128 + ((gk ^ (arow & 7)) << 4);
                ldsm_x4(a_hi[mb], sA + off);
                ldsm_x4(a_lo[mb], sA + 16384 + off);
            }
#pragma unroll
            for (int nb = 0; nb < 8; ++nb) {
                uint32_t brow = nwarp * 64 + nb * 8 + (lane & 7);
                int gk = ks * 2 + ((lane >> 3) & 1);
                uint32_t off = brow * 128 + ((gk ^ (brow & 7)) << 4);
                uint32_t b_hi[2], b_lo[2];
                ldsm_x2(b_hi, sB + off);
                ldsm_x2(b_lo, sB + 16384 + off);
#pragma unroll
                for (int mb = 0; mb < 2; ++mb) {
                    mma_bf16(acc[mb][nb], a_hi[mb], b_hi);
                    mma_bf16(acc[mb][nb], a_hi[mb], b_lo);
                    mma_bf16(acc[mb][nb], a_lo[mb], b_hi);
                }
            }
        }
    }

    // epilogue: + bias, store fp32
#pragma unroll
    for (int nb = 0; nb < 8; ++nb) {
        const int col = n0 + nwarp * 64 + nb * 8 + (lane & 3) * 2;
        float2 bv = *(const float2*)(bias + col);
#pragma unroll
        for (int mb = 0; mb < 2; ++mb)
#pragma unroll
            for (int rh = 0; rh < 2; ++rh) {
                int row = m0 + mwarp * 32 + mb * 16 + rh * 8 + (lane >> 2);
                float2 o = make_float2(acc[mb][nb][rh * 2] + bv.x,
                                       acc[mb][nb][rh * 2 + 1] + bv.y);
                *(float2*)(g_pre + (size_t)row * GG + col) = o;
            }
    }
}

// ---------------------------------------------------------------------------
// Kernel E: barrier init
// ---------------------------------------------------------------------------
__global__ void bar_init_kernel() {
    if (threadIdx.x == 0) g_bar = 0u;
}

// ---------------------------------------------------------------------------
// Kernel F: persistent LSTM (all 256 steps, device-wide barrier between steps)
// CTA: 64 batch x [4 gates x 32 j]; grid (32, 4) = 128 CTAs (1/SM, 1 wave).
// Per step: Gates = pre + Hhi@Uhi + Hhi@Ulo + Hlo@Uhi, fused cell update.
// ---------------------------------------------------------------------------
__global__ __launch_bounds__(256, 1) void lstm_persistent(
    float* __restrict__ hidden,      // [B][T][H]
    float* __restrict__ c_state,     // [B][H]
    float* __restrict__ h_final) {   // [B][H]
    extern __shared__ char dsm[];
    const int tid = threadIdx.x;
    const int wid = tid >> 5;
    const int lane = tid & 31;
    const int jt = blockIdx.x;       // 0..31
    const int mt = blockIdx.y;       // 0..3
    const int mwarp = wid >> 1;      // 0..3
    const int jwarp = wid & 1;       // 0..1
    const uint32_t smem0 = (uint32_t)__cvta_generic_to_shared(dsm);

    for (int t = 0; t < TT; ++t) {
        float acc[4][2][4];
#pragma unroll
        for (int g = 0; g < 4; ++g)
#pragma unroll
            for (int nb = 0; nb < 2; ++nb)
#pragma unroll
                for (int r = 0; r < 4; ++r) acc[g][nb][r] = 0.f;

        if (t > 0) {
            const __nv_bfloat16* hphi = g_hbf_hi[(t - 1) & 1];
            const __nv_bfloat16* hplo = g_hbf_lo[(t - 1) & 1];

            auto load_chunk = [&](int c, int s) {
                const int k0 = c * KC;
                const uint32_t sb = smem0 + s * STAGE_BYTES;
#pragma unroll
                for (int i = 0; i < 4; ++i) {
                    int ga = i * 256 + tid;
                    int mat = ga >> 9;
                    int row = (ga >> 3) & 63;
                    int gk = ga & 7;
                    const __nv_bfloat16* src = (mat ? hplo : hphi) +
                        (size_t)(mt * 64 + row) * HH + k0 + gk * 8;
                    uint32_t dst = sb + mat * 8192 + row * 128 + ((gk ^ (row & 7)) << 4);
                    cp_async16(dst, src);
                }
#pragma unroll
                for (int i = 0; i < 8; ++i) {
                    int gb = i * 256 + tid;
                    int mat = gb >> 10;
                    int row = (gb >> 3) & 127;
                    int gk = gb & 7;
                    int grow = (row >> 5) * HH + jt * 32 + (row & 31);
                    const __nv_bfloat16* src = (mat ? g_ut_lo : g_ut_hi) +
                        (size_t)grow * HH + k0 + gk * 8;
                    uint32_t dst = sb + 16384 + mat * 16384 + row * 128 +
                                   ((gk ^ (row & 7)) << 4);
                    cp_async16(dst, src);
                }
                asm volatile("cp.async.commit_group;" ::: "memory");
            };

            load_chunk(0, 0);
            asm volatile("cp.async.wait_group 0;" ::: "memory");
            __syncthreads();

            const uint32_t arow = mwarp * 16 + (lane & 15);
            const uint32_t brow_base = jwarp * 16 + (lane & 7);

            for (int c = 0; c < NCH; ++c) {
                const int s = c & 1;
                if (c + 1 < NCH) load_chunk(c + 1, s ^ 1);
                const uint32_t sb = smem0 + s * STAGE_BYTES;
#pragma unroll
                for (int ks = 0; ks < KC / 16; ++ks) {
                    uint32_t a_hi[4], a_lo[4];
                    {
                        int gk = ks * 2 + (lane >> 4);
                        uint32_t off = arow * 128 + ((gk ^ (arow & 7)) << 4);
                        ldsm_x4(a_hi, sb + off);
                        ldsm_x4(a_lo, sb + 8192 + off);
                    }
#pragma unroll
                    for (int g = 0; g < 4; ++g) {
#pragma unroll
                        for (int nb = 0; nb < 2; ++nb) {
                            uint32_t row = g * 32 + brow_base + nb * 8;
                            int gk = ks * 2 + ((lane >> 3) & 1);
                            uint32_t off = row * 128 + ((gk ^ (row & 7)) << 4);
                            uint32_t b_hi[2], b_lo[2];
                            ldsm_x2(b_hi, sb + 16384 + off);
                            ldsm_x2(b_lo, sb + 32768 + off);
                            mma_bf16(acc[g][nb], a_hi, b_hi);
                            mma_bf16(acc[g][nb], a_hi, b_lo);
                            mma_bf16(acc[g][nb], a_lo, b_hi);
                        }
                    }
                }
                if (c + 1 < NCH) {
                    asm volatile("cp.async.wait_group 0;" ::: "memory");
                    __syncthreads();
                }
            }
        }

        // ---- fused cell-update epilogue ----
        const int b_base = mt * 64 + mwarp * 16 + (lane >> 2);
#pragma unroll
        for (int rh = 0; rh < 2; ++rh) {
            const int b = b_base + rh * 8;
            const float* prow = g_pre + ((size_t)b * TT + t) * GG;
            float* crow = c_state + (size_t)b * HH;
            float* hrow = hidden + ((size_t)b * TT + t) * HH;
            __nv_bfloat16* bh = g_hbf_hi[t & 1] + (size_t)b * HH;
            __nv_bfloat16* bl = g_hbf_lo[t & 1] + (size_t)b * HH;
#pragma unroll
            for (int nb = 0; nb < 2; ++nb) {
                const int j = jt * 32 + jwarp * 16 + nb * 8 + (lane & 3) * 2;
                float2 pi = *(const float2*)(prow + 0 * HH + j);
                float2 pf = *(const float2*)(prow + 1 * HH + j);
                float2 pg = *(const float2*)(prow + 2 * HH + j);
                float2 po = *(const float2*)(prow + 3 * HH + j);
                float2 co = (t > 0) ? *(const float2*)(crow + j)
                                    : make_float2(0.f, 0.f);
                const int r0 = rh * 2;
                float i0 = sigmoidf_(acc[0][nb][r0]     + pi.x);
                float i1 = sigmoidf_(acc[0][nb][r0 + 1] + pi.y);
                float f0 = sigmoidf_(acc[1][nb][r0]     + pf.x);
                float f1 = sigmoidf_(acc[1][nb][r0 + 1] + pf.y);
                float g0 = tanhf(acc[2][nb][r0]     + pg.x);
                float g1 = tanhf(acc[2][nb][r0 + 1] + pg.y);
                float o0 = sigmoidf_(acc[3][nb][r0]     + po.x);
                float o1 = sigmoidf_(acc[3][nb][r0 + 1] + po.y);
                float cn0 = f0 * co.x + i0 * g0;
                float cn1 = f1 * co.y + i1 * g1;
                float hn0 = o0 * tanhf(cn0);
                float hn1 = o1 * tanhf(cn1);
                *(float2*)(crow + j) = make_float2(cn0, cn1);
                *(float2*)(hrow + j) = make_float2(hn0, hn1);
                __nv_bfloat16 h0h = __float2bfloat16(hn0);
                __nv_bfloat16 h1h = __float2bfloat16(hn1);
                __nv_bfloat16 h0l = __float2bfloat16(hn0 - __bfloat162float(h0h));
                __nv_bfloat16 h1l = __float2bfloat16(hn1 - __bfloat162float(h1h));
                *(__nv_bfloat162*)(bh + j) = __nv_bfloat162(h0h, h1h);
                *(__nv_bfloat162*)(bl + j) = __nv_bfloat162(h0l, h1l);
                if (t == TT - 1)
                    *(float2*)(h_final + (size_t)b * HH + j) = make_float2(hn0, hn1);
            }
        }

        // ---- device-wide step barrier ----
        if (t < TT - 1) {
            __threadfence();
            __syncthreads();
            if (tid == 0) {
                atomicAdd(&g_bar, 1u);
                const unsigned target = 128u * (unsigned)(t + 1);
                while (atomicAdd(&g_bar, 0u) < target) {}
            }
            __syncthreads();
            __threadfence();
        }
    }
}

// ---------------------------------------------------------------------------
// Kernel G: y_pred[b] = h_final[b,:] . fc_w + fc_b
// ---------------------------------------------------------------------------
__global__ void fc_kernel(const float* __restrict__ h_final,
                          const float* __restrict__ fc_w,
                          const float* __restrict__ fc_b,
                          float* __restrict__ y_pred) {
    int b = blockIdx.x;
    int tid = threadIdx.x;
    float s = 0.f;
    for (int k = tid; k < HH; k += 256)
        s += h_final[b * HH + k] * fc_w[k];
#pragma unroll
    for (int off = 16; off > 0; off >>= 1)
        s += __shfl_down_sync(0xffffffffu, s, off);
    __shared__ float red[8];
    if ((tid & 31) == 0) red[tid >> 5] = s;
    __syncthreads();
    if (tid == 0) {
        float tot = 0.f;
#pragma unroll
        for (int w = 0; w < 8; ++w) tot += red[w];
        y_pred[b] = tot + fc_b[0];
    }
}

// ---------------------------------------------------------------------------
extern "C" void kernel_launch(void* const* d_in, const int* in_sizes, int n_in,
                              void* d_out, int out_size) {
    const float* X    = (const float*)d_in[0];
    const float* W    = (const float*)d_in[1];
    const float* U    = (const float*)d_in[2];
    const float* bias = (const float*)d_in[3];
    const float* Wy   = (const float*)d_in[4];
    const float* fc_w = (const float*)d_in[5];
    const float* fc_b = (const float*)d_in[6];

    float* out = (float*)d_out;
    // output layout: y_pred[256] | hidden_seq[B*T*H] | h_t[B*H] | c_t[B*H]
    float* y_pred  = out;
    float* hidden  = out + 256;
    float* h_final = hidden + (size_t)BB * TT * HH;
    float* c_state = h_final + (size_t)BB * HH;

    cudaFuncSetAttribute(lstm_persistent, cudaFuncAttributeMaxDynamicSharedMemorySize,
                         DYN_SMEM);
    cudaFuncSetAttribute(pre_gemm_mma, cudaFuncAttributeMaxDynamicSharedMemorySize,
                         PRE_SMEM);

    wt_split_kernel<<<dim3(ID / 32, GG / 32), 256>>>(W, Wy);
    u_split_kernel<<<dim3(HH / 32, GG / 32), 256>>>(U);
    x_split_kernel<<<(BB * TT * ID) / 4 / 256, 256>>>(X);
    pre_gemm_mma<<<dim3(GG / 128, (BB * TT) / 128), 256, PRE_SMEM>>>(bias);
    bar_init_kernel<<<1, 32>>>();
    lstm_persistent<<<dim3(HH / 32, BB / 64), 256, DYN_SMEM>>>(hidden, c_state,
                                                               h_final);
    fc_kernel<<<BB, 256>>>(h_final, fc_w, fc_b, y_pred);
}